// round 1
// baseline (speedup 1.0000x reference)
#include <cuda_runtime.h>
#include <math.h>

#define B_ 8
#define N_ 1024
#define C_ 768
#define H_ 12
#define D_ 64
#define SCALE_ 0.125f  /* 64^-0.5 */

// Scratch (no allocations allowed): QKV projection output and attention output.
__device__ float g_qkv[B_ * N_ * 3 * C_];   // [8192, 2304]  ~75.5 MB
__device__ float g_attn[B_ * N_ * C_];      // [8192, 768]   ~25.2 MB

// ---------------------------------------------------------------------------
// Tiled fp32 GEMM: C[M,N] = A[M,K] @ B[K,N] (+ bias). 64x64 tile, 256 thr,
// 4x4 microtile per thread. M%64==0, N%64==0, K%16==0 (true for our shapes).
// ---------------------------------------------------------------------------
template <bool BIAS>
__global__ void gemm64_kernel(const float* __restrict__ A,
                              const float* __restrict__ Bm,
                              const float* __restrict__ bias,
                              float* __restrict__ Cm,
                              int M, int Nn, int K) {
    __shared__ float As[64][17];   // pad to kill bank conflicts
    __shared__ float Bs[16][68];

    const int tx = threadIdx.x;            // 0..15
    const int ty = threadIdx.y;            // 0..15
    const int tid = ty * 16 + tx;          // 0..255
    const int row0 = blockIdx.y * 64;
    const int col0 = blockIdx.x * 64;

    float acc[4][4];
#pragma unroll
    for (int i = 0; i < 4; i++)
#pragma unroll
        for (int j = 0; j < 4; j++) acc[i][j] = 0.f;

    const int ai = tid >> 2;                 // 0..63
    const int ak = (tid & 3) * 4;            // 0,4,8,12
    const int bk = tid >> 4;                 // 0..15
    const int bj = (tid & 15) * 4;           // 0..60

    for (int k0 = 0; k0 < K; k0 += 16) {
        // load A tile 64x16 (float4, coalesced)
        {
            const float4 v = *reinterpret_cast<const float4*>(
                &A[(size_t)(row0 + ai) * K + k0 + ak]);
            As[ai][ak + 0] = v.x; As[ai][ak + 1] = v.y;
            As[ai][ak + 2] = v.z; As[ai][ak + 3] = v.w;
        }
        // load B tile 16x64 (float4, coalesced)
        {
            const float4 v = *reinterpret_cast<const float4*>(
                &Bm[(size_t)(k0 + bk) * Nn + col0 + bj]);
            Bs[bk][bj + 0] = v.x; Bs[bk][bj + 1] = v.y;
            Bs[bk][bj + 2] = v.z; Bs[bk][bj + 3] = v.w;
        }
        __syncthreads();

#pragma unroll
        for (int k = 0; k < 16; k++) {
            float a[4], b[4];
#pragma unroll
            for (int ii = 0; ii < 4; ii++) a[ii] = As[ty * 4 + ii][k];
#pragma unroll
            for (int jj = 0; jj < 4; jj++) b[jj] = Bs[k][tx * 4 + jj];
#pragma unroll
            for (int ii = 0; ii < 4; ii++)
#pragma unroll
                for (int jj = 0; jj < 4; jj++)
                    acc[ii][jj] = fmaf(a[ii], b[jj], acc[ii][jj]);
        }
        __syncthreads();
    }

#pragma unroll
    for (int ii = 0; ii < 4; ii++) {
        const int r = row0 + ty * 4 + ii;
#pragma unroll
        for (int jj = 0; jj < 4; jj++) {
            const int c = col0 + tx * 4 + jj;
            float v = acc[ii][jj];
            if (BIAS) v += bias[c];
            Cm[(size_t)r * Nn + c] = v;
        }
    }
}

// ---------------------------------------------------------------------------
// Flash-style attention. Grid: (N/64 q-tiles, B*H). Block: 256 threads.
// Online softmax, K/V streamed in 64-row tiles through dynamic smem.
// qkv layout: row m=b*N+n, cols [q(0:768) | k(768:1536) | v(1536:2304)],
// head h occupies cols h*64..h*64+63 within each third.
// Output layout: g_attn[b*N+n][h*64+d]  (== transpose(0,2,1,3).reshape)
// ---------------------------------------------------------------------------
#define LDQ 65
#define LDV 68
#define ATTN_SMEM ((3 * 64 * LDQ + 64 * LDV) * 4)   // 67,328 bytes

__global__ void attn_kernel(const float* __restrict__ qkv,
                            float* __restrict__ out) {
    extern __shared__ float sm[];
    float* Qs = sm;                   // [64][65]
    float* Ks = Qs + 64 * LDQ;        // [64][65]
    float* Ss = Ks + 64 * LDQ;        // [64][65]
    float* Vs = Ss + 64 * LDQ;        // [64][68]  (float4-aligned reads)

    const int tid = threadIdx.x;          // 0..255
    const int bh  = blockIdx.y;
    const int b   = bh / H_;
    const int h   = bh % H_;
    const int qt  = blockIdx.x;

    // Load Q tile [64,64] (float4 global loads)
    for (int idx = tid; idx < 64 * 16; idx += 256) {
        const int i = idx >> 4;
        const int d4 = (idx & 15) * 4;
        const float4 v = *reinterpret_cast<const float4*>(
            &qkv[(size_t)(b * N_ + qt * 64 + i) * (3 * C_) + h * D_ + d4]);
        Qs[i * LDQ + d4 + 0] = v.x; Qs[i * LDQ + d4 + 1] = v.y;
        Qs[i * LDQ + d4 + 2] = v.z; Qs[i * LDQ + d4 + 3] = v.w;
    }

    // S-compute mapping: 4x4 microtile
    const int i0 = (tid >> 4) * 4;     // 0..60
    const int j0 = (tid & 15) * 4;     // 0..60
    // softmax/PV mapping: row r, 16 columns starting at cq
    const int r  = tid >> 2;           // 0..63
    const int cq = (tid & 3) * 16;     // 0,16,32,48

    float m = -INFINITY, l = 0.f;
    float o[16];
#pragma unroll
    for (int c = 0; c < 16; c++) o[c] = 0.f;

    for (int kt = 0; kt < N_ / 64; kt++) {
        // Load K and V tiles [64,64]
        for (int idx = tid; idx < 64 * 16; idx += 256) {
            const int j = idx >> 4;
            const int d4 = (idx & 15) * 4;
            const size_t rowbase = (size_t)(b * N_ + kt * 64 + j) * (3 * C_);
            const float4 kv = *reinterpret_cast<const float4*>(
                &qkv[rowbase + C_ + h * D_ + d4]);
            Ks[j * LDQ + d4 + 0] = kv.x; Ks[j * LDQ + d4 + 1] = kv.y;
            Ks[j * LDQ + d4 + 2] = kv.z; Ks[j * LDQ + d4 + 3] = kv.w;
            const float4 vv = *reinterpret_cast<const float4*>(
                &qkv[rowbase + 2 * C_ + h * D_ + d4]);
            *reinterpret_cast<float4*>(&Vs[j * LDV + d4]) = vv;
        }
        __syncthreads();

        // S = Q @ K^T * SCALE
        float s[4][4];
#pragma unroll
        for (int ii = 0; ii < 4; ii++)
#pragma unroll
            for (int jj = 0; jj < 4; jj++) s[ii][jj] = 0.f;
#pragma unroll
        for (int k = 0; k < 64; k++) {
            float a[4], bb[4];
#pragma unroll
            for (int ii = 0; ii < 4; ii++) a[ii] = Qs[(i0 + ii) * LDQ + k];
#pragma unroll
            for (int jj = 0; jj < 4; jj++) bb[jj] = Ks[(j0 + jj) * LDQ + k];
#pragma unroll
            for (int ii = 0; ii < 4; ii++)
#pragma unroll
                for (int jj = 0; jj < 4; jj++)
                    s[ii][jj] = fmaf(a[ii], bb[jj], s[ii][jj]);
        }
#pragma unroll
        for (int ii = 0; ii < 4; ii++)
#pragma unroll
            for (int jj = 0; jj < 4; jj++)
                Ss[(i0 + ii) * LDQ + j0 + jj] = s[ii][jj] * SCALE_;
        __syncthreads();

        // Online softmax for row r over this tile's 64 scores.
        // 4 consecutive lanes (tid&3) share a row -> shfl reductions.
        float pv[16];
        float tm = -INFINITY;
#pragma unroll
        for (int c = 0; c < 16; c++) {
            pv[c] = Ss[r * LDQ + cq + c];
            tm = fmaxf(tm, pv[c]);
        }
        tm = fmaxf(tm, __shfl_xor_sync(0xffffffffu, tm, 1));
        tm = fmaxf(tm, __shfl_xor_sync(0xffffffffu, tm, 2));
        const float mnew = fmaxf(m, tm);
        const float corr = __expf(m - mnew);
        float ps = 0.f;
#pragma unroll
        for (int c = 0; c < 16; c++) {
            pv[c] = __expf(pv[c] - mnew);
            ps += pv[c];
            Ss[r * LDQ + cq + c] = pv[c];
        }
        ps += __shfl_xor_sync(0xffffffffu, ps, 1);
        ps += __shfl_xor_sync(0xffffffffu, ps, 2);
        l = l * corr + ps;
        m = mnew;
#pragma unroll
        for (int c = 0; c < 16; c++) o[c] *= corr;
        __syncthreads();

        // O[r, cq:cq+16] += P[r,:] @ V[:, cq:cq+16]
#pragma unroll 4
        for (int j = 0; j < 64; j++) {
            const float p = Ss[r * LDQ + j];
            const float4* vrow =
                reinterpret_cast<const float4*>(&Vs[j * LDV + cq]);
            const float4 v0 = vrow[0], v1 = vrow[1], v2 = vrow[2], v3 = vrow[3];
            o[0]  = fmaf(p, v0.x, o[0]);  o[1]  = fmaf(p, v0.y, o[1]);
            o[2]  = fmaf(p, v0.z, o[2]);  o[3]  = fmaf(p, v0.w, o[3]);
            o[4]  = fmaf(p, v1.x, o[4]);  o[5]  = fmaf(p, v1.y, o[5]);
            o[6]  = fmaf(p, v1.z, o[6]);  o[7]  = fmaf(p, v1.w, o[7]);
            o[8]  = fmaf(p, v2.x, o[8]);  o[9]  = fmaf(p, v2.y, o[9]);
            o[10] = fmaf(p, v2.z, o[10]); o[11] = fmaf(p, v2.w, o[11]);
            o[12] = fmaf(p, v3.x, o[12]); o[13] = fmaf(p, v3.y, o[13]);
            o[14] = fmaf(p, v3.z, o[14]); o[15] = fmaf(p, v3.w, o[15]);
        }
        __syncthreads();
    }

    const float inv = 1.f / l;
    const size_t obase = (size_t)(b * N_ + qt * 64 + r) * C_ + h * D_ + cq;
#pragma unroll
    for (int c = 0; c < 16; c++) out[obase + c] = o[c] * inv;
}

// ---------------------------------------------------------------------------
// Launch
// ---------------------------------------------------------------------------
extern "C" void kernel_launch(void* const* d_in, const int* in_sizes, int n_in,
                              void* d_out, int out_size) {
    const float* x      = (const float*)d_in[0];   // [8,1024,768]
    const float* w_qkv  = (const float*)d_in[1];   // [768,2304]
    const float* w_proj = (const float*)d_in[2];   // [768,768]
    const float* b_proj = (const float*)d_in[3];   // [768]
    float* out = (float*)d_out;                    // [8,1024,768]

    float* qkv = nullptr;
    float* att = nullptr;
    cudaGetSymbolAddress((void**)&qkv, g_qkv);
    cudaGetSymbolAddress((void**)&att, g_attn);

    // Allow >48KB dynamic smem for the attention kernel (idempotent).
    cudaFuncSetAttribute(attn_kernel,
                         cudaFuncAttributeMaxDynamicSharedMemorySize,
                         ATTN_SMEM);

    const int M = B_ * N_;   // 8192

    // 1) QKV projection: [8192,768] @ [768,2304]
    {
        dim3 grid((3 * C_) / 64, M / 64);
        dim3 block(16, 16);
        gemm64_kernel<false><<<grid, block>>>(x, w_qkv, nullptr, qkv,
                                              M, 3 * C_, C_);
    }

    // 2) Attention
    {
        dim3 grid(N_ / 64, B_ * H_);
        attn_kernel<<<grid, 256, ATTN_SMEM>>>(qkv, att);
    }

    // 3) Output projection + bias: [8192,768] @ [768,768]
    {
        dim3 grid(C_ / 64, M / 64);
        dim3 block(16, 16);
        gemm64_kernel<true><<<grid, block>>>(att, w_proj, b_proj, out,
                                             M, C_, C_);
    }
}

// round 2
// speedup vs baseline: 1.8110x; 1.8110x over previous
#include <cuda_runtime.h>
#include <math.h>

#define B_ 8
#define N_ 1024
#define C_ 768
#define H_ 12
#define D_ 64
#define QKVC_ (3 * C_)
#define SCALE_ 0.125f  /* 64^-0.5 */

// Scratch (no allocations allowed)
__device__ float g_qkv[B_ * N_ * QKVC_];    // [8192, 2304]
__device__ float g_attn[B_ * N_ * C_];      // [8192, 768]

// ---------------------------------------------------------------------------
// Tiled fp32 GEMM: C[M,N] = A[M,K] @ B[K,N] (+ bias).
// 128x128 block tile, 256 threads, 8x8 microtile (4+4 split at +64),
// A stored transposed in smem, register prefetch of next K-slab.
// Requires M%128==0, N%128==0, K%16==0.
// ---------------------------------------------------------------------------
template <bool BIAS>
__global__ __launch_bounds__(256, 2)
void gemm128_kernel(const float* __restrict__ A,
                    const float* __restrict__ Bm,
                    const float* __restrict__ bias,
                    float* __restrict__ Cm,
                    int M, int Nn, int K) {
    __shared__ float AsT[16][132];   // [k][row], padded
    __shared__ float Bs[16][132];    // [k][col], padded

    const int tid = threadIdx.x;
    const int row0 = blockIdx.y * 128;
    const int col0 = blockIdx.x * 128;

    // compute mapping: rows {i0..i0+3, i0+64..i0+67}, cols {j0..j0+3, j0+64..}
    const int i0 = (tid >> 4) * 4;
    const int j0 = (tid & 15) * 4;

    float acc[8][8];
#pragma unroll
    for (int i = 0; i < 8; i++)
#pragma unroll
        for (int j = 0; j < 8; j++) acc[i][j] = 0.f;

    float4 pa[2], pb[2];

    // loader mappings
    // A: fid in [0,512): arow = fid>>2 (0..127), ak = (fid&3)*4
    // B: fid in [0,512): bk = fid>>5 (0..15), bj = (fid&31)*4
#define LOAD_AB(k0)                                                          \
    {                                                                        \
        _Pragma("unroll")                                                    \
        for (int l = 0; l < 2; l++) {                                        \
            const int fid = tid + l * 256;                                   \
            const int arow = fid >> 2, ak = (fid & 3) * 4;                   \
            pa[l] = *reinterpret_cast<const float4*>(                        \
                &A[(size_t)(row0 + arow) * K + (k0) + ak]);                  \
            const int bk = fid >> 5, bj = (fid & 31) * 4;                    \
            pb[l] = *reinterpret_cast<const float4*>(                        \
                &Bm[(size_t)((k0) + bk) * Nn + col0 + bj]);                  \
        }                                                                    \
    }

    LOAD_AB(0);

    for (int k0 = 0; k0 < K; k0 += 16) {
        // store prefetched slab
#pragma unroll
        for (int l = 0; l < 2; l++) {
            const int fid = tid + l * 256;
            const int arow = fid >> 2, ak = (fid & 3) * 4;
            const float* av = reinterpret_cast<const float*>(&pa[l]);
            AsT[ak + 0][arow] = av[0];
            AsT[ak + 1][arow] = av[1];
            AsT[ak + 2][arow] = av[2];
            AsT[ak + 3][arow] = av[3];
            const int bk = fid >> 5, bj = (fid & 31) * 4;
            *reinterpret_cast<float4*>(&Bs[bk][bj]) = pb[l];
        }
        __syncthreads();

        if (k0 + 16 < K) LOAD_AB(k0 + 16);

#pragma unroll
        for (int k = 0; k < 16; k++) {
            float a[8], b[8];
            *reinterpret_cast<float4*>(&a[0]) =
                *reinterpret_cast<const float4*>(&AsT[k][i0]);
            *reinterpret_cast<float4*>(&a[4]) =
                *reinterpret_cast<const float4*>(&AsT[k][i0 + 64]);
            *reinterpret_cast<float4*>(&b[0]) =
                *reinterpret_cast<const float4*>(&Bs[k][j0]);
            *reinterpret_cast<float4*>(&b[4]) =
                *reinterpret_cast<const float4*>(&Bs[k][j0 + 64]);
#pragma unroll
            for (int ii = 0; ii < 8; ii++)
#pragma unroll
                for (int jj = 0; jj < 8; jj++)
                    acc[ii][jj] = fmaf(a[ii], b[jj], acc[ii][jj]);
        }
        __syncthreads();
    }
#undef LOAD_AB

    // epilogue
    float bv[8];
    if (BIAS) {
        *reinterpret_cast<float4*>(&bv[0]) =
            *reinterpret_cast<const float4*>(&bias[col0 + j0]);
        *reinterpret_cast<float4*>(&bv[4]) =
            *reinterpret_cast<const float4*>(&bias[col0 + j0 + 64]);
    }
#pragma unroll
    for (int ii = 0; ii < 8; ii++) {
        const int r = row0 + ((ii < 4) ? (i0 + ii) : (i0 + 64 + ii - 4));
        float* crow = &Cm[(size_t)r * Nn + col0];
        float4 v0, v1;
        float* v0f = reinterpret_cast<float*>(&v0);
        float* v1f = reinterpret_cast<float*>(&v1);
#pragma unroll
        for (int jj = 0; jj < 4; jj++) {
            v0f[jj] = acc[ii][jj]     + (BIAS ? bv[jj]     : 0.f);
            v1f[jj] = acc[ii][jj + 4] + (BIAS ? bv[jj + 4] : 0.f);
        }
        *reinterpret_cast<float4*>(&crow[j0])      = v0;
        *reinterpret_cast<float4*>(&crow[j0 + 64]) = v1;
    }
}

// ---------------------------------------------------------------------------
// Flash attention v2. Grid: (N/64, B*H). Block: 256 threads.
// Q,K stored transposed (d-major) -> S-loop vectorized; softmax in registers
// via half-warp shuffles; P written transposed once; PV vectorized;
// next K/V tile prefetched into registers during PV.
// ---------------------------------------------------------------------------
#define LDA_ 68
#define ATTN_SMEM (4 * 64 * LDA_ * 4)   // 69,632 bytes

__global__ __launch_bounds__(256)
void attn_kernel(const float* __restrict__ qkv, float* __restrict__ out) {
    extern __shared__ float sm[];
    float* QT = sm;                    // [d][i]
    float* KT = QT + 64 * LDA_;        // [d][j]
    float* Vs = KT + 64 * LDA_;        // [j][d]
    float* PT = Vs + 64 * LDA_;        // [j][i]

    const int tid = threadIdx.x;
    const int b = blockIdx.y / H_;
    const int h = blockIdx.y % H_;
    const int qt = blockIdx.x;

    const size_t qrow0 = (size_t)(b * N_ + qt * 64);
    const int qoff = h * D_;

    // --- load Q transposed (scale folded) ---
#pragma unroll
    for (int l = 0; l < 4; l++) {
        const int fid = tid + l * 256;
        const int i = fid & 63;
        const int d4 = (fid >> 6) * 4;
        const float4 v = *reinterpret_cast<const float4*>(
            &qkv[(qrow0 + i) * QKVC_ + qoff + d4]);
        QT[(d4 + 0) * LDA_ + i] = v.x * SCALE_;
        QT[(d4 + 1) * LDA_ + i] = v.y * SCALE_;
        QT[(d4 + 2) * LDA_ + i] = v.z * SCALE_;
        QT[(d4 + 3) * LDA_ + i] = v.w * SCALE_;
    }

    // K/V prefetch registers
    float4 kreg[4], vreg[4];
#define LOAD_KV(kt)                                                          \
    {                                                                        \
        const size_t krow0 = (size_t)(b * N_ + (kt) * 64);                   \
        _Pragma("unroll")                                                    \
        for (int l = 0; l < 4; l++) {                                        \
            const int fid = tid + l * 256;                                   \
            const int jk = fid & 63;                                         \
            const int dk = (fid >> 6) * 4;                                   \
            kreg[l] = *reinterpret_cast<const float4*>(                      \
                &qkv[(krow0 + jk) * QKVC_ + C_ + qoff + dk]);                \
            const int jv = fid >> 4;                                         \
            const int dv = (fid & 15) * 4;                                   \
            vreg[l] = *reinterpret_cast<const float4*>(                      \
                &qkv[(krow0 + jv) * QKVC_ + 2 * C_ + qoff + dv]);            \
        }                                                                    \
    }
#define STORE_KV()                                                          \
    {                                                                        \
        _Pragma("unroll")                                                   \
        for (int l = 0; l < 4; l++) {                                       \
            const int fid = tid + l * 256;                                  \
            const int jk = fid & 63;                                        \
            const int dk = (fid >> 6) * 4;                                  \
            const float* kv = reinterpret_cast<const float*>(&kreg[l]);     \
            KT[(dk + 0) * LDA_ + jk] = kv[0];                               \
            KT[(dk + 1) * LDA_ + jk] = kv[1];                               \
            KT[(dk + 2) * LDA_ + jk] = kv[2];                               \
            KT[(dk + 3) * LDA_ + jk] = kv[3];                               \
            const int jv = fid >> 4;                                        \
            const int dv = (fid & 15) * 4;                                  \
            *reinterpret_cast<float4*>(&Vs[jv * LDA_ + dv]) = vreg[l];      \
        }                                                                   \
    }

    LOAD_KV(0);
    STORE_KV();
    __syncthreads();

    const int i0 = (tid >> 4) * 4;     // query rows (shared by 16-lane group)
    const int j0 = (tid & 15) * 4;     // key cols for S
    const int d0 = (tid & 15) * 4;     // output dims for PV

    float m[4], l[4], o[4][4];
#pragma unroll
    for (int ii = 0; ii < 4; ii++) {
        m[ii] = -INFINITY; l[ii] = 0.f;
#pragma unroll
        for (int cc = 0; cc < 4; cc++) o[ii][cc] = 0.f;
    }

    for (int kt = 0; kt < N_ / 64; kt++) {
        // ---- S = (Q*scale) @ K^T ----
        float s[4][4];
#pragma unroll
        for (int ii = 0; ii < 4; ii++)
#pragma unroll
            for (int jj = 0; jj < 4; jj++) s[ii][jj] = 0.f;
#pragma unroll 8
        for (int k = 0; k < 64; k++) {
            float a[4], bb[4];
            *reinterpret_cast<float4*>(a) =
                *reinterpret_cast<const float4*>(&QT[k * LDA_ + i0]);
            *reinterpret_cast<float4*>(bb) =
                *reinterpret_cast<const float4*>(&KT[k * LDA_ + j0]);
#pragma unroll
            for (int ii = 0; ii < 4; ii++)
#pragma unroll
                for (int jj = 0; jj < 4; jj++)
                    s[ii][jj] = fmaf(a[ii], bb[jj], s[ii][jj]);
        }

        // ---- online softmax in registers (16-lane groups share rows) ----
#pragma unroll
        for (int ii = 0; ii < 4; ii++) {
            float tm = fmaxf(fmaxf(s[ii][0], s[ii][1]),
                             fmaxf(s[ii][2], s[ii][3]));
            tm = fmaxf(tm, __shfl_xor_sync(0xffffffffu, tm, 1));
            tm = fmaxf(tm, __shfl_xor_sync(0xffffffffu, tm, 2));
            tm = fmaxf(tm, __shfl_xor_sync(0xffffffffu, tm, 4));
            tm = fmaxf(tm, __shfl_xor_sync(0xffffffffu, tm, 8));
            const float mn = fmaxf(m[ii], tm);
            const float corr = __expf(m[ii] - mn);
            m[ii] = mn;
            float ps = 0.f;
#pragma unroll
            for (int jj = 0; jj < 4; jj++) {
                s[ii][jj] = __expf(s[ii][jj] - mn);
                ps += s[ii][jj];
            }
            ps += __shfl_xor_sync(0xffffffffu, ps, 1);
            ps += __shfl_xor_sync(0xffffffffu, ps, 2);
            ps += __shfl_xor_sync(0xffffffffu, ps, 4);
            ps += __shfl_xor_sync(0xffffffffu, ps, 8);
            l[ii] = l[ii] * corr + ps;
#pragma unroll
            for (int cc = 0; cc < 4; cc++) o[ii][cc] *= corr;
        }

        // ---- write P transposed: PT[j][i] ----
#pragma unroll
        for (int jj = 0; jj < 4; jj++) {
            float4 pv;
            pv.x = s[0][jj]; pv.y = s[1][jj]; pv.z = s[2][jj]; pv.w = s[3][jj];
            *reinterpret_cast<float4*>(&PT[(j0 + jj) * LDA_ + i0]) = pv;
        }
        __syncthreads();   // all P visible; KT no longer needed this tile

        if (kt + 1 < N_ / 64) LOAD_KV(kt + 1);

        // ---- O += P @ V ----
#pragma unroll 8
        for (int j = 0; j < 64; j++) {
            float a[4], vv[4];
            *reinterpret_cast<float4*>(a) =
                *reinterpret_cast<const float4*>(&PT[j * LDA_ + i0]);
            *reinterpret_cast<float4*>(vv) =
                *reinterpret_cast<const float4*>(&Vs[j * LDA_ + d0]);
#pragma unroll
            for (int ii = 0; ii < 4; ii++)
#pragma unroll
                for (int cc = 0; cc < 4; cc++)
                    o[ii][cc] = fmaf(a[ii], vv[cc], o[ii][cc]);
        }
        __syncthreads();   // done reading KT/Vs/PT

        if (kt + 1 < N_ / 64) {
            STORE_KV();
            __syncthreads();
        }
    }
#undef LOAD_KV
#undef STORE_KV

    // ---- write O / l ----
#pragma unroll
    for (int ii = 0; ii < 4; ii++) {
        const float inv = 1.f / l[ii];
        float4 w;
        w.x = o[ii][0] * inv; w.y = o[ii][1] * inv;
        w.z = o[ii][2] * inv; w.w = o[ii][3] * inv;
        *reinterpret_cast<float4*>(
            &out[(qrow0 + i0 + ii) * C_ + qoff + d0]) = w;
    }
}

// ---------------------------------------------------------------------------
// Launch
// ---------------------------------------------------------------------------
extern "C" void kernel_launch(void* const* d_in, const int* in_sizes, int n_in,
                              void* d_out, int out_size) {
    const float* x      = (const float*)d_in[0];
    const float* w_qkv  = (const float*)d_in[1];
    const float* w_proj = (const float*)d_in[2];
    const float* b_proj = (const float*)d_in[3];
    float* out = (float*)d_out;

    float* qkv = nullptr;
    float* att = nullptr;
    cudaGetSymbolAddress((void**)&qkv, g_qkv);
    cudaGetSymbolAddress((void**)&att, g_attn);

    cudaFuncSetAttribute(attn_kernel,
                         cudaFuncAttributeMaxDynamicSharedMemorySize,
                         ATTN_SMEM);

    const int M = B_ * N_;   // 8192

    // 1) QKV projection: [8192,768] @ [768,2304]
    {
        dim3 grid(QKVC_ / 128, M / 128);
        gemm128_kernel<false><<<grid, 256>>>(x, w_qkv, nullptr, qkv,
                                             M, QKVC_, C_);
    }
    // 2) Attention
    {
        dim3 grid(N_ / 64, B_ * H_);
        attn_kernel<<<grid, 256, ATTN_SMEM>>>(qkv, out /*unused*/ == out ? att : att);
    }
    // 3) Output projection + bias: [8192,768] @ [768,768]
    {
        dim3 grid(C_ / 128, M / 128);
        gemm128_kernel<true><<<grid, 256>>>(att, w_proj, b_proj, out,
                                            M, C_, C_);
    }
}

// round 4
// speedup vs baseline: 2.3449x; 1.2948x over previous
#include <cuda_runtime.h>
#include <cuda_bf16.h>
#include <math.h>
#include <stdint.h>

#define B_ 8
#define N_ 1024
#define C_ 768
#define H_ 12
#define D_ 64
#define QKVC_ (3 * C_)
#define M_ (B_ * N_)
#define SCALE_ 0.125f

// ----------------------------- scratch ------------------------------------
__device__ float g_qkv[M_ * QKVC_];
__device__ float g_attn[M_ * C_];
__device__ __nv_bfloat16 g_xhi[M_ * C_],     g_xlo[M_ * C_];
__device__ __nv_bfloat16 g_whiT[QKVC_ * C_], g_wloT[QKVC_ * C_];
__device__ __nv_bfloat16 g_phiT[C_ * C_],    g_ploT[C_ * C_];
__device__ __nv_bfloat16 g_ahi[M_ * C_],     g_alo[M_ * C_];

// ----------------------------- helpers ------------------------------------
__device__ __forceinline__ uint32_t smem_u32(const void* p) {
    uint32_t a;
    asm("{ .reg .u64 t; cvta.to.shared.u64 t, %1; cvt.u32.u64 %0, t; }"
        : "=r"(a) : "l"(p));
    return a;
}
__device__ __forceinline__ void cp16(uint32_t s, const void* g) {
    asm volatile("cp.async.cg.shared.global [%0], [%1], 16;"
                 :: "r"(s), "l"(g) : "memory");
}
#define CP_COMMIT() asm volatile("cp.async.commit_group;" ::: "memory")
#define CP_WAIT(n)  asm volatile("cp.async.wait_group %0;" :: "n"(n) : "memory")

__device__ __forceinline__ void ldsm_x4(uint32_t* f, uint32_t a) {
    asm volatile("ldmatrix.sync.aligned.m8n8.x4.shared.b16 {%0,%1,%2,%3}, [%4];"
                 : "=r"(f[0]), "=r"(f[1]), "=r"(f[2]), "=r"(f[3]) : "r"(a));
}
__device__ __forceinline__ void ldsm_x2(uint32_t* f, uint32_t a) {
    asm volatile("ldmatrix.sync.aligned.m8n8.x2.shared.b16 {%0,%1}, [%2];"
                 : "=r"(f[0]), "=r"(f[1]) : "r"(a));
}
__device__ __forceinline__ void mma16816(float* d, const uint32_t* a,
                                         const uint32_t* b) {
    asm volatile(
        "mma.sync.aligned.m16n8k16.row.col.f32.bf16.bf16.f32 "
        "{%0,%1,%2,%3}, {%4,%5,%6,%7}, {%8,%9}, {%0,%1,%2,%3};"
        : "+f"(d[0]), "+f"(d[1]), "+f"(d[2]), "+f"(d[3])
        : "r"(a[0]), "r"(a[1]), "r"(a[2]), "r"(a[3]), "r"(b[0]), "r"(b[1]));
}

// ----------------------------- split kernels ------------------------------
__global__ void split_ew(const float4* __restrict__ s,
                         __nv_bfloat16* __restrict__ hi,
                         __nv_bfloat16* __restrict__ lo, int n4) {
    int i = blockIdx.x * blockDim.x + threadIdx.x;
    if (i >= n4) return;
    float4 v = s[i];
    float a[4] = {v.x, v.y, v.z, v.w};
    __align__(8) __nv_bfloat16 h[4];
    __align__(8) __nv_bfloat16 l[4];
#pragma unroll
    for (int j = 0; j < 4; j++) {
        h[j] = __float2bfloat16(a[j]);
        l[j] = __float2bfloat16(a[j] - __bfloat162float(h[j]));
    }
    *reinterpret_cast<uint2*>(hi + (size_t)i * 4) = *reinterpret_cast<uint2*>(h);
    *reinterpret_cast<uint2*>(lo + (size_t)i * 4) = *reinterpret_cast<uint2*>(l);
}

// w[K,N] -> hiT/loT [N,K]
__global__ void split_transpose(const float* __restrict__ w,
                                __nv_bfloat16* __restrict__ hiT,
                                __nv_bfloat16* __restrict__ loT, int K, int N) {
    __shared__ float t[32][33];
    const int n0 = blockIdx.x * 32, k0 = blockIdx.y * 32;
    for (int r = threadIdx.y; r < 32; r += 8)
        t[r][threadIdx.x] = w[(size_t)(k0 + r) * N + n0 + threadIdx.x];
    __syncthreads();
    for (int r = threadIdx.y; r < 32; r += 8) {
        float v = t[threadIdx.x][r];
        __nv_bfloat16 h = __float2bfloat16(v);
        __nv_bfloat16 l = __float2bfloat16(v - __bfloat162float(h));
        size_t o = (size_t)(n0 + r) * K + k0 + threadIdx.x;
        hiT[o] = h; loT[o] = l;
    }
}

// ----------------------------- mma.sync GEMM -------------------------------
// C[M,Nn] = Ahi@Bhi^T + Ahi@Blo^T + Alo@Bhi^T (+bias). B stored [Nn,K].
// 128x128 block tile, 8 warps (2m x 4n), warp tile 64x32, BK=32,
// cp.async 2-stage double buffer. Smem rows padded to 80B (ldmatrix
// conflict-free: row*5 mod 8 distinct).
#define BK_ 32
#define LROW_ 80                       // bytes per smem row (40 bf16)
#define MATB_ (128 * LROW_)            // 10240 B per matrix tile
#define STGB_ (4 * MATB_)              // 40960 B per stage
#define GEMM_SMEM (2 * STGB_)          // 81920 B

template <bool BIAS>
__global__ __launch_bounds__(256, 1)
void mma_gemm(const __nv_bfloat16* __restrict__ Ahi,
              const __nv_bfloat16* __restrict__ Alo,
              const __nv_bfloat16* __restrict__ BhiT,
              const __nv_bfloat16* __restrict__ BloT,
              const float* __restrict__ bias,
              float* __restrict__ Cm, int Nn, int K) {
    extern __shared__ char smem[];
    const uint32_t sb = smem_u32(smem);
    const int tid = threadIdx.x;
    const int wid = tid >> 5;
    const int lane = tid & 31;
    const int row0 = blockIdx.y * 128;
    const int col0 = blockIdx.x * 128;
    const int wm = (wid >> 2) * 64;     // warp m offset in tile
    const int wn = (wid & 3) * 32;      // warp n offset in tile

    float acc[4][4][4];
#pragma unroll
    for (int i = 0; i < 4; i++)
#pragma unroll
        for (int j = 0; j < 4; j++)
#pragma unroll
            for (int k = 0; k < 4; k++) acc[i][j][k] = 0.f;

#define LOAD_STAGE(cc, ss)                                                   \
    {                                                                        \
        const uint32_t base = sb + (ss) * STGB_;                             \
        const int k0 = (cc) * BK_;                                           \
        _Pragma("unroll")                                                    \
        for (int t = 0; t < 2; t++) {                                        \
            const int idx = tid + t * 256;                                   \
            const int r = idx >> 2, ch = idx & 3;                            \
            const uint32_t off = (uint32_t)(r * LROW_ + ch * 16);            \
            const size_t ga = (size_t)(row0 + r) * K + k0 + ch * 8;          \
            const size_t gb = (size_t)(col0 + r) * K + k0 + ch * 8;          \
            cp16(base + off,             Ahi + ga);                          \
            cp16(base + MATB_ + off,     Alo + ga);                          \
            cp16(base + 2 * MATB_ + off, BhiT + gb);                         \
            cp16(base + 3 * MATB_ + off, BloT + gb);                         \
        }                                                                    \
        CP_COMMIT();                                                         \
    }

    const int nch = K / BK_;    // 24 for K=768
    LOAD_STAGE(0, 0);

    for (int c = 0; c < nch; c++) {
        const int cur = c & 1;
        if (c + 1 < nch) {
            LOAD_STAGE(c + 1, 1 - cur);
            CP_WAIT(1);
        } else {
            CP_WAIT(0);
        }
        __syncthreads();

        const uint32_t stg = sb + cur * STGB_;
#pragma unroll
        for (int kk = 0; kk < 2; kk++) {
            // load fragments
            uint32_t ah[4][4], al[4][4], bh[4][2], bl[4][2];
            const uint32_t acol = (uint32_t)((kk * 16 + (lane >> 4) * 8) * 2);
            const uint32_t bcol = (uint32_t)((kk * 16 + ((lane >> 3) & 1) * 8) * 2);
#pragma unroll
            for (int mt = 0; mt < 4; mt++) {
                const uint32_t arow =
                    (uint32_t)((wm + mt * 16 + (lane & 15)) * LROW_);
                ldsm_x4(ah[mt], stg + arow + acol);
                ldsm_x4(al[mt], stg + MATB_ + arow + acol);
            }
#pragma unroll
            for (int nt = 0; nt < 4; nt++) {
                const uint32_t brow =
                    (uint32_t)((wn + nt * 8 + (lane & 7)) * LROW_);
                ldsm_x2(bh[nt], stg + 2 * MATB_ + brow + bcol);
                ldsm_x2(bl[nt], stg + 3 * MATB_ + brow + bcol);
            }
            // mma: hi*hi + hi*lo + lo*hi
#pragma unroll
            for (int mt = 0; mt < 4; mt++)
#pragma unroll
                for (int nt = 0; nt < 4; nt++) {
                    mma16816(acc[mt][nt], ah[mt], bh[nt]);
                    mma16816(acc[mt][nt], ah[mt], bl[nt]);
                    mma16816(acc[mt][nt], al[mt], bh[nt]);
                }
        }
        __syncthreads();
    }
#undef LOAD_STAGE

    // ---- epilogue: direct float2 stores ----
    const int g = lane >> 2, t4 = lane & 3;
#pragma unroll
    for (int nt = 0; nt < 4; nt++) {
        const int col = col0 + wn + nt * 8 + t4 * 2;
        float b0 = 0.f, b1 = 0.f;
        if (BIAS) { b0 = bias[col]; b1 = bias[col + 1]; }
#pragma unroll
        for (int mt = 0; mt < 4; mt++) {
            const int ra = row0 + wm + mt * 16 + g;
            float2 v0 = make_float2(acc[mt][nt][0] + b0, acc[mt][nt][1] + b1);
            float2 v1 = make_float2(acc[mt][nt][2] + b0, acc[mt][nt][3] + b1);
            *reinterpret_cast<float2*>(&Cm[(size_t)ra * Nn + col]) = v0;
            *reinterpret_cast<float2*>(&Cm[(size_t)(ra + 8) * Nn + col]) = v1;
        }
    }
}

// ----------------------------- flash attention (SIMT, verified R2) --------
#define LDA_ 68
#define ATTN_SMEM (4 * 64 * LDA_ * 4)

__global__ __launch_bounds__(256)
void attn_kernel(const float* __restrict__ qkv, float* __restrict__ out) {
    extern __shared__ float sm[];
    float* QT = sm;
    float* KT = QT + 64 * LDA_;
    float* Vs = KT + 64 * LDA_;
    float* PT = Vs + 64 * LDA_;

    const int tid = threadIdx.x;
    const int b = blockIdx.y / H_;
    const int h = blockIdx.y % H_;
    const int qt = blockIdx.x;

    const size_t qrow0 = (size_t)(b * N_ + qt * 64);
    const int qoff = h * D_;

#pragma unroll
    for (int l = 0; l < 4; l++) {
        const int fid = tid + l * 256;
        const int i = fid & 63;
        const int d4 = (fid >> 6) * 4;
        const float4 v = *reinterpret_cast<const float4*>(
            &qkv[(qrow0 + i) * QKVC_ + qoff + d4]);
        QT[(d4 + 0) * LDA_ + i] = v.x * SCALE_;
        QT[(d4 + 1) * LDA_ + i] = v.y * SCALE_;
        QT[(d4 + 2) * LDA_ + i] = v.z * SCALE_;
        QT[(d4 + 3) * LDA_ + i] = v.w * SCALE_;
    }

    float4 kreg[4], vreg[4];
#define LOAD_KV(kt)                                                          \
    {                                                                        \
        const size_t krow0 = (size_t)(b * N_ + (kt) * 64);                   \
        _Pragma("unroll")                                                    \
        for (int l = 0; l < 4; l++) {                                        \
            const int fid = tid + l * 256;                                   \
            const int jk = fid & 63;                                         \
            const int dk = (fid >> 6) * 4;                                   \
            kreg[l] = *reinterpret_cast<const float4*>(                      \
                &qkv[(krow0 + jk) * QKVC_ + C_ + qoff + dk]);                \
            const int jv = fid >> 4;                                         \
            const int dv = (fid & 15) * 4;                                   \
            vreg[l] = *reinterpret_cast<const float4*>(                      \
                &qkv[(krow0 + jv) * QKVC_ + 2 * C_ + qoff + dv]);            \
        }                                                                    \
    }
#define STORE_KV()                                                          \
    {                                                                        \
        _Pragma("unroll")                                                   \
        for (int l = 0; l < 4; l++) {                                       \
            const int fid = tid + l * 256;                                  \
            const int jk = fid & 63;                                        \
            const int dk = (fid >> 6) * 4;                                  \
            const float* kv = reinterpret_cast<const float*>(&kreg[l]);     \
            KT[(dk + 0) * LDA_ + jk] = kv[0];                               \
            KT[(dk + 1) * LDA_ + jk] = kv[1];                               \
            KT[(dk + 2) * LDA_ + jk] = kv[2];                               \
            KT[(dk + 3) * LDA_ + jk] = kv[3];                               \
            const int jv = fid >> 4;                                        \
            const int dv = (fid & 15) * 4;                                  \
            *reinterpret_cast<float4*>(&Vs[jv * LDA_ + dv]) = vreg[l];      \
        }                                                                   \
    }

    LOAD_KV(0);
    STORE_KV();
    __syncthreads();

    const int i0 = (tid >> 4) * 4;
    const int j0 = (tid & 15) * 4;
    const int d0 = (tid & 15) * 4;

    float m[4], l[4], o[4][4];
#pragma unroll
    for (int ii = 0; ii < 4; ii++) {
        m[ii] = -INFINITY; l[ii] = 0.f;
#pragma unroll
        for (int cc = 0; cc < 4; cc++) o[ii][cc] = 0.f;
    }

    for (int kt = 0; kt < N_ / 64; kt++) {
        float s[4][4];
#pragma unroll
        for (int ii = 0; ii < 4; ii++)
#pragma unroll
            for (int jj = 0; jj < 4; jj++) s[ii][jj] = 0.f;
#pragma unroll 8
        for (int k = 0; k < 64; k++) {
            float a[4], bb[4];
            *reinterpret_cast<float4*>(a) =
                *reinterpret_cast<const float4*>(&QT[k * LDA_ + i0]);
            *reinterpret_cast<float4*>(bb) =
                *reinterpret_cast<const float4*>(&KT[k * LDA_ + j0]);
#pragma unroll
            for (int ii = 0; ii < 4; ii++)
#pragma unroll
                for (int jj = 0; jj < 4; jj++)
                    s[ii][jj] = fmaf(a[ii], bb[jj], s[ii][jj]);
        }

#pragma unroll
        for (int ii = 0; ii < 4; ii++) {
            float tm = fmaxf(fmaxf(s[ii][0], s[ii][1]),
                             fmaxf(s[ii][2], s[ii][3]));
            tm = fmaxf(tm, __shfl_xor_sync(0xffffffffu, tm, 1));
            tm = fmaxf(tm, __shfl_xor_sync(0xffffffffu, tm, 2));
            tm = fmaxf(tm, __shfl_xor_sync(0xffffffffu, tm, 4));
            tm = fmaxf(tm, __shfl_xor_sync(0xffffffffu, tm, 8));
            const float mn = fmaxf(m[ii], tm);
            const float corr = __expf(m[ii] - mn);
            m[ii] = mn;
            float ps = 0.f;
#pragma unroll
            for (int jj = 0; jj < 4; jj++) {
                s[ii][jj] = __expf(s[ii][jj] - mn);
                ps += s[ii][jj];
            }
            ps += __shfl_xor_sync(0xffffffffu, ps, 1);
            ps += __shfl_xor_sync(0xffffffffu, ps, 2);
            ps += __shfl_xor_sync(0xffffffffu, ps, 4);
            ps += __shfl_xor_sync(0xffffffffu, ps, 8);
            l[ii] = l[ii] * corr + ps;
#pragma unroll
            for (int cc = 0; cc < 4; cc++) o[ii][cc] *= corr;
        }

#pragma unroll
        for (int jj = 0; jj < 4; jj++) {
            float4 pv;
            pv.x = s[0][jj]; pv.y = s[1][jj]; pv.z = s[2][jj]; pv.w = s[3][jj];
            *reinterpret_cast<float4*>(&PT[(j0 + jj) * LDA_ + i0]) = pv;
        }
        __syncthreads();

        if (kt + 1 < N_ / 64) LOAD_KV(kt + 1);

#pragma unroll 8
        for (int j = 0; j < 64; j++) {
            float a[4], vv[4];
            *reinterpret_cast<float4*>(a) =
                *reinterpret_cast<const float4*>(&PT[j * LDA_ + i0]);
            *reinterpret_cast<float4*>(vv) =
                *reinterpret_cast<const float4*>(&Vs[j * LDA_ + d0]);
#pragma unroll
            for (int ii = 0; ii < 4; ii++)
#pragma unroll
                for (int cc = 0; cc < 4; cc++)
                    o[ii][cc] = fmaf(a[ii], vv[cc], o[ii][cc]);
        }
        __syncthreads();

        if (kt + 1 < N_ / 64) {
            STORE_KV();
            __syncthreads();
        }
    }
#undef LOAD_KV
#undef STORE_KV

#pragma unroll
    for (int ii = 0; ii < 4; ii++) {
        const float inv = 1.f / l[ii];
        float4 w;
        w.x = o[ii][0] * inv; w.y = o[ii][1] * inv;
        w.z = o[ii][2] * inv; w.w = o[ii][3] * inv;
        *reinterpret_cast<float4*>(
            &out[(qrow0 + i0 + ii) * C_ + qoff + d0]) = w;
    }
}

// ----------------------------- launch -------------------------------------
extern "C" void kernel_launch(void* const* d_in, const int* in_sizes, int n_in,
                              void* d_out, int out_size) {
    const float* x      = (const float*)d_in[0];
    const float* w_qkv  = (const float*)d_in[1];
    const float* w_proj = (const float*)d_in[2];
    const float* b_proj = (const float*)d_in[3];
    float* out = (float*)d_out;

    float *qkv, *att;
    __nv_bfloat16 *xhi, *xlo, *whiT, *wloT, *phiT, *ploT, *ahi, *alo;
    cudaGetSymbolAddress((void**)&qkv,  g_qkv);
    cudaGetSymbolAddress((void**)&att,  g_attn);
    cudaGetSymbolAddress((void**)&xhi,  g_xhi);
    cudaGetSymbolAddress((void**)&xlo,  g_xlo);
    cudaGetSymbolAddress((void**)&whiT, g_whiT);
    cudaGetSymbolAddress((void**)&wloT, g_wloT);
    cudaGetSymbolAddress((void**)&phiT, g_phiT);
    cudaGetSymbolAddress((void**)&ploT, g_ploT);
    cudaGetSymbolAddress((void**)&ahi,  g_ahi);
    cudaGetSymbolAddress((void**)&alo,  g_alo);

    cudaFuncSetAttribute(attn_kernel,
                         cudaFuncAttributeMaxDynamicSharedMemorySize, ATTN_SMEM);
    cudaFuncSetAttribute(mma_gemm<false>,
                         cudaFuncAttributeMaxDynamicSharedMemorySize, GEMM_SMEM);
    cudaFuncSetAttribute(mma_gemm<true>,
                         cudaFuncAttributeMaxDynamicSharedMemorySize, GEMM_SMEM);

    // 0) splits
    {
        int n4 = (M_ * C_) / 4;
        split_ew<<<(n4 + 255) / 256, 256>>>((const float4*)x, xhi, xlo, n4);
        dim3 blk(32, 8);
        dim3 g1(QKVC_ / 32, C_ / 32);
        split_transpose<<<g1, blk>>>(w_qkv, whiT, wloT, C_, QKVC_);
        dim3 g2(C_ / 32, C_ / 32);
        split_transpose<<<g2, blk>>>(w_proj, phiT, ploT, C_, C_);
    }
    // 1) QKV projection (tensor cores via mma.sync)
    {
        dim3 grid(QKVC_ / 128, M_ / 128);
        mma_gemm<false><<<grid, 256, GEMM_SMEM>>>(xhi, xlo, whiT, wloT,
                                                  nullptr, qkv, QKVC_, C_);
    }
    // 2) attention (SIMT flash)
    {
        dim3 grid(N_ / 64, B_ * H_);
        attn_kernel<<<grid, 256, ATTN_SMEM>>>(qkv, att);
    }
    // 3) split attention output, then output projection (tensor cores)
    {
        int n4 = (M_ * C_) / 4;
        split_ew<<<(n4 + 255) / 256, 256>>>((const float4*)att, ahi, alo, n4);
        dim3 grid(C_ / 128, M_ / 128);
        mma_gemm<true><<<grid, 256, GEMM_SMEM>>>(ahi, alo, phiT, ploT,
                                                 b_proj, out, C_, C_);
    }
}

// round 5
// speedup vs baseline: 4.3621x; 1.8602x over previous
#include <cuda_runtime.h>
#include <cuda_bf16.h>
#include <math.h>
#include <stdint.h>

#define B_ 8
#define N_ 1024
#define C_ 768
#define H_ 12
#define D_ 64
#define QKVC_ (3 * C_)
#define M_ (B_ * N_)

// ----------------------------- scratch ------------------------------------
__device__ __nv_bfloat16 g_xhi[M_ * C_],     g_xlo[M_ * C_];
__device__ __nv_bfloat16 g_whiT[QKVC_ * C_], g_wloT[QKVC_ * C_];
__device__ __nv_bfloat16 g_phiT[C_ * C_],    g_ploT[C_ * C_];
__device__ __nv_bfloat16 g_qkvhi[M_ * QKVC_], g_qkvlo[M_ * QKVC_];
__device__ __nv_bfloat16 g_ahi[M_ * C_],     g_alo[M_ * C_];

// ----------------------------- helpers ------------------------------------
__device__ __forceinline__ uint32_t smem_u32(const void* p) {
    uint32_t a;
    asm("{ .reg .u64 t; cvta.to.shared.u64 t, %1; cvt.u32.u64 %0, t; }"
        : "=r"(a) : "l"(p));
    return a;
}
__device__ __forceinline__ void cp16(uint32_t s, const void* g) {
    asm volatile("cp.async.cg.shared.global [%0], [%1], 16;"
                 :: "r"(s), "l"(g) : "memory");
}
#define CP_COMMIT() asm volatile("cp.async.commit_group;" ::: "memory")
#define CP_WAIT(n)  asm volatile("cp.async.wait_group %0;" :: "n"(n) : "memory")

__device__ __forceinline__ void ldsm_x4(uint32_t* f, uint32_t a) {
    asm volatile("ldmatrix.sync.aligned.m8n8.x4.shared.b16 {%0,%1,%2,%3}, [%4];"
                 : "=r"(f[0]), "=r"(f[1]), "=r"(f[2]), "=r"(f[3]) : "r"(a));
}
__device__ __forceinline__ void ldsm_x4t(uint32_t* f, uint32_t a) {
    asm volatile("ldmatrix.sync.aligned.m8n8.x4.trans.shared.b16 {%0,%1,%2,%3}, [%4];"
                 : "=r"(f[0]), "=r"(f[1]), "=r"(f[2]), "=r"(f[3]) : "r"(a));
}
__device__ __forceinline__ void ldsm_x2(uint32_t* f, uint32_t a) {
    asm volatile("ldmatrix.sync.aligned.m8n8.x2.shared.b16 {%0,%1}, [%2];"
                 : "=r"(f[0]), "=r"(f[1]) : "r"(a));
}
__device__ __forceinline__ void mma16816(float* d, const uint32_t* a,
                                         const uint32_t* b) {
    asm volatile(
        "mma.sync.aligned.m16n8k16.row.col.f32.bf16.bf16.f32 "
        "{%0,%1,%2,%3}, {%4,%5,%6,%7}, {%8,%9}, {%0,%1,%2,%3};"
        : "+f"(d[0]), "+f"(d[1]), "+f"(d[2]), "+f"(d[3])
        : "r"(a[0]), "r"(a[1]), "r"(a[2]), "r"(a[3]), "r"(b[0]), "r"(b[1]));
}
__device__ __forceinline__ uint32_t pk2(float f0, float f1) {
    __nv_bfloat162 h = __floats2bfloat162_rn(f0, f1);
    return *reinterpret_cast<uint32_t*>(&h);
}

// ----------------------------- split kernels ------------------------------
__global__ void split_ew(const float4* __restrict__ s,
                         __nv_bfloat16* __restrict__ hi,
                         __nv_bfloat16* __restrict__ lo, int n4) {
    int i = blockIdx.x * blockDim.x + threadIdx.x;
    if (i >= n4) return;
    float4 v = s[i];
    float a[4] = {v.x, v.y, v.z, v.w};
    __align__(8) __nv_bfloat16 h[4];
    __align__(8) __nv_bfloat16 l[4];
#pragma unroll
    for (int j = 0; j < 4; j++) {
        h[j] = __float2bfloat16(a[j]);
        l[j] = __float2bfloat16(a[j] - __bfloat162float(h[j]));
    }
    *reinterpret_cast<uint2*>(hi + (size_t)i * 4) = *reinterpret_cast<uint2*>(h);
    *reinterpret_cast<uint2*>(lo + (size_t)i * 4) = *reinterpret_cast<uint2*>(l);
}

__global__ void split_transpose(const float* __restrict__ w,
                                __nv_bfloat16* __restrict__ hiT,
                                __nv_bfloat16* __restrict__ loT, int K, int N) {
    __shared__ float t[32][33];
    const int n0 = blockIdx.x * 32, k0 = blockIdx.y * 32;
    for (int r = threadIdx.y; r < 32; r += 8)
        t[r][threadIdx.x] = w[(size_t)(k0 + r) * N + n0 + threadIdx.x];
    __syncthreads();
    for (int r = threadIdx.y; r < 32; r += 8) {
        float v = t[threadIdx.x][r];
        __nv_bfloat16 h = __float2bfloat16(v);
        __nv_bfloat16 l = __float2bfloat16(v - __bfloat162float(h));
        size_t o = (size_t)(n0 + r) * K + k0 + threadIdx.x;
        hiT[o] = h; loT[o] = l;
    }
}

// ----------------------------- mma.sync GEMM -------------------------------
#define BK_ 32
#define LROW_ 80
#define MATB_ (128 * LROW_)
#define STGB_ (4 * MATB_)
#define GEMM_SMEM (2 * STGB_)

// SPLITOUT: write bf16 hi/lo (cols < scale_cols scaled by 0.125) instead of fp32
template <bool BIAS, bool SPLITOUT>
__global__ __launch_bounds__(256, 1)
void mma_gemm(const __nv_bfloat16* __restrict__ Ahi,
              const __nv_bfloat16* __restrict__ Alo,
              const __nv_bfloat16* __restrict__ BhiT,
              const __nv_bfloat16* __restrict__ BloT,
              const float* __restrict__ bias,
              float* __restrict__ Cf,
              __nv_bfloat16* __restrict__ Chi,
              __nv_bfloat16* __restrict__ Clo,
              int scale_cols, int Nn, int K) {
    extern __shared__ char smem[];
    const uint32_t sb = smem_u32(smem);
    const int tid = threadIdx.x;
    const int wid = tid >> 5;
    const int lane = tid & 31;
    const int row0 = blockIdx.y * 128;
    const int col0 = blockIdx.x * 128;
    const int wm = (wid >> 2) * 64;
    const int wn = (wid & 3) * 32;

    float acc[4][4][4];
#pragma unroll
    for (int i = 0; i < 4; i++)
#pragma unroll
        for (int j = 0; j < 4; j++)
#pragma unroll
            for (int k = 0; k < 4; k++) acc[i][j][k] = 0.f;

#define LOAD_STAGE(cc, ss)                                                   \
    {                                                                        \
        const uint32_t base = sb + (ss) * STGB_;                             \
        const int k0 = (cc) * BK_;                                           \
        _Pragma("unroll")                                                    \
        for (int t = 0; t < 2; t++) {                                        \
            const int idx = tid + t * 256;                                   \
            const int r = idx >> 2, ch = idx & 3;                            \
            const uint32_t off = (uint32_t)(r * LROW_ + ch * 16);            \
            const size_t ga = (size_t)(row0 + r) * K + k0 + ch * 8;          \
            const size_t gb = (size_t)(col0 + r) * K + k0 + ch * 8;          \
            cp16(base + off,             Ahi + ga);                          \
            cp16(base + MATB_ + off,     Alo + ga);                          \
            cp16(base + 2 * MATB_ + off, BhiT + gb);                         \
            cp16(base + 3 * MATB_ + off, BloT + gb);                         \
        }                                                                    \
        CP_COMMIT();                                                         \
    }

    const int nch = K / BK_;
    LOAD_STAGE(0, 0);

    for (int c = 0; c < nch; c++) {
        const int cur = c & 1;
        if (c + 1 < nch) {
            LOAD_STAGE(c + 1, 1 - cur);
            CP_WAIT(1);
        } else {
            CP_WAIT(0);
        }
        __syncthreads();

        const uint32_t stg = sb + cur * STGB_;
#pragma unroll
        for (int kk = 0; kk < 2; kk++) {
            uint32_t ah[4][4], al[4][4], bh[4][2], bl[4][2];
            const uint32_t acol = (uint32_t)((kk * 16 + (lane >> 4) * 8) * 2);
            const uint32_t bcol = (uint32_t)((kk * 16 + ((lane >> 3) & 1) * 8) * 2);
#pragma unroll
            for (int mt = 0; mt < 4; mt++) {
                const uint32_t arow =
                    (uint32_t)((wm + mt * 16 + (lane & 15)) * LROW_);
                ldsm_x4(ah[mt], stg + arow + acol);
                ldsm_x4(al[mt], stg + MATB_ + arow + acol);
            }
#pragma unroll
            for (int nt = 0; nt < 4; nt++) {
                const uint32_t brow =
                    (uint32_t)((wn + nt * 8 + (lane & 7)) * LROW_);
                ldsm_x2(bh[nt], stg + 2 * MATB_ + brow + bcol);
                ldsm_x2(bl[nt], stg + 3 * MATB_ + brow + bcol);
            }
#pragma unroll
            for (int mt = 0; mt < 4; mt++)
#pragma unroll
                for (int nt = 0; nt < 4; nt++) {
                    mma16816(acc[mt][nt], ah[mt], bh[nt]);
                    mma16816(acc[mt][nt], ah[mt], bl[nt]);
                    mma16816(acc[mt][nt], al[mt], bh[nt]);
                }
        }
        __syncthreads();
    }
#undef LOAD_STAGE

    const int g = lane >> 2, t4 = lane & 3;
#pragma unroll
    for (int nt = 0; nt < 4; nt++) {
        const int col = col0 + wn + nt * 8 + t4 * 2;
        if (SPLITOUT) {
            const float sc = (col < scale_cols) ? 0.125f : 1.0f;
#pragma unroll
            for (int mt = 0; mt < 4; mt++) {
                const int ra = row0 + wm + mt * 16 + g;
#pragma unroll
                for (int half = 0; half < 2; half++) {
                    const int r = ra + half * 8;
                    const float v0 = acc[mt][nt][half * 2 + 0] * sc;
                    const float v1 = acc[mt][nt][half * 2 + 1] * sc;
                    __nv_bfloat16 h0 = __float2bfloat16(v0);
                    __nv_bfloat16 h1 = __float2bfloat16(v1);
                    const float l0 = v0 - __bfloat162float(h0);
                    const float l1 = v1 - __bfloat162float(h1);
                    const size_t off = (size_t)r * Nn + col;
                    *reinterpret_cast<uint32_t*>(Chi + off) =
                        pk2(__bfloat162float(h0), __bfloat162float(h1));
                    *reinterpret_cast<uint32_t*>(Clo + off) = pk2(l0, l1);
                }
            }
        } else {
            float b0 = 0.f, b1 = 0.f;
            if (BIAS) { b0 = bias[col]; b1 = bias[col + 1]; }
#pragma unroll
            for (int mt = 0; mt < 4; mt++) {
                const int ra = row0 + wm + mt * 16 + g;
                float2 v0 = make_float2(acc[mt][nt][0] + b0, acc[mt][nt][1] + b1);
                float2 v1 = make_float2(acc[mt][nt][2] + b0, acc[mt][nt][3] + b1);
                *reinterpret_cast<float2*>(&Cf[(size_t)ra * Nn + col]) = v0;
                *reinterpret_cast<float2*>(&Cf[(size_t)(ra + 8) * Nn + col]) = v1;
            }
        }
    }
}

// ----------------------------- mma flash attention -------------------------
// CTA per (bh, 128-row q tile). 8 warps, warp tile = 16 q-rows x full 128 keys.
// Split-bf16 everywhere (hi*hi + hi*lo + lo*hi). Q pre-scaled by 0.125 in
// the QKV GEMM epilogue. Output written as split bf16 (ahi/alo).
#define ATT_LD 144
#define ATT_MAT 18432                      // 128 * 144
#define ATT_STG0 (2 * ATT_MAT)             // after Qhi,Qlo
#define ATT_STGSZ (4 * ATT_MAT)            // Khi,Klo,Vhi,Vlo
#define ATT_SMEM (ATT_STG0 + 2 * ATT_STGSZ)  // 184320

__global__ __launch_bounds__(256, 1)
void attn_mma(const __nv_bfloat16* __restrict__ qhi,
              const __nv_bfloat16* __restrict__ qlo,
              __nv_bfloat16* __restrict__ ohi,
              __nv_bfloat16* __restrict__ olo) {
    extern __shared__ char smem[];
    const uint32_t sb = smem_u32(smem);
    const int tid = threadIdx.x, wid = tid >> 5, lane = tid & 31;
    const int b = blockIdx.y / H_, h = blockIdx.y % H_;
    const int q0 = blockIdx.x * 128;
    const size_t rowbase = (size_t)b * N_;

    // ---- load Q (hi/lo) ----
#pragma unroll
    for (int t = 0; t < 8; t++) {
        const int idx = tid + t * 256;
        const int mat = idx >> 10, rem = idx & 1023;
        const int r = rem >> 3, c = rem & 7;
        const uint32_t so = sb + mat * ATT_MAT + r * ATT_LD + c * 16;
        const __nv_bfloat16* src =
            (mat ? qlo : qhi) + ((rowbase + q0 + r) * QKVC_ + h * D_ + c * 8);
        cp16(so, src);
    }

#define LOAD_STAGE_ATT(ktile, ss)                                            \
    {                                                                        \
        const uint32_t base = sb + ATT_STG0 + (ss) * ATT_STGSZ;              \
        const size_t krow = rowbase + (ktile) * 128;                         \
        _Pragma("unroll")                                                    \
        for (int t = 0; t < 16; t++) {                                       \
            const int idx = tid + t * 256;                                   \
            const int mat = idx >> 10, rem = idx & 1023;                     \
            const int r = rem >> 3, c = rem & 7;                             \
            const uint32_t so = base + mat * ATT_MAT + r * ATT_LD + c * 16;  \
            const __nv_bfloat16* sp = ((mat & 1) ? qlo : qhi) +              \
                ((krow + r) * QKVC_ + ((mat >> 1) ? 2 * C_ : C_) +           \
                 h * D_ + c * 8);                                            \
            cp16(so, sp);                                                    \
        }                                                                    \
        CP_COMMIT();                                                         \
    }

    LOAD_STAGE_ATT(0, 0);

    float m_lo = -INFINITY, m_hi = -INFINITY, l_lo = 0.f, l_hi = 0.f;
    float o[8][4];
#pragma unroll
    for (int i = 0; i < 8; i++)
#pragma unroll
        for (int j = 0; j < 4; j++) o[i][j] = 0.f;

    const uint32_t qa =
        sb + (wid * 16 + (lane & 15)) * ATT_LD + ((lane >> 4) * 8) * 2;

    for (int kt = 0; kt < N_ / 128; kt++) {
        CP_WAIT(0);
        __syncthreads();
        if (kt + 1 < N_ / 128) LOAD_STAGE_ATT(kt + 1, (kt + 1) & 1);

        const uint32_t stg = sb + ATT_STG0 + (kt & 1) * ATT_STGSZ;

        // ---- S = Q @ K^T (3-pass split) ----
        float s[16][4];
#pragma unroll
        for (int nt = 0; nt < 16; nt++)
#pragma unroll
            for (int j = 0; j < 4; j++) s[nt][j] = 0.f;

#pragma unroll
        for (int k4 = 0; k4 < 4; k4++) {
            uint32_t qh[4], ql[4];
            ldsm_x4(qh, qa + k4 * 32);
            ldsm_x4(ql, qa + ATT_MAT + k4 * 32);
            const uint32_t ka = stg + (lane & 7) * ATT_LD +
                                (k4 * 16 + ((lane >> 3) & 1) * 8) * 2;
#pragma unroll
            for (int nt = 0; nt < 16; nt++) {
                uint32_t kh[2], kl[2];
                ldsm_x2(kh, ka + nt * 8 * ATT_LD);
                ldsm_x2(kl, ka + ATT_MAT + nt * 8 * ATT_LD);
                mma16816(s[nt], qh, kh);
                mma16816(s[nt], qh, kl);
                mma16816(s[nt], ql, kh);
            }
        }

        // ---- online softmax (rows = lane>>2 and +8; quad shfl reduce) ----
        float tmlo = -INFINITY, tmhi = -INFINITY;
#pragma unroll
        for (int nt = 0; nt < 16; nt++) {
            tmlo = fmaxf(tmlo, fmaxf(s[nt][0], s[nt][1]));
            tmhi = fmaxf(tmhi, fmaxf(s[nt][2], s[nt][3]));
        }
        tmlo = fmaxf(tmlo, __shfl_xor_sync(0xffffffffu, tmlo, 1));
        tmlo = fmaxf(tmlo, __shfl_xor_sync(0xffffffffu, tmlo, 2));
        tmhi = fmaxf(tmhi, __shfl_xor_sync(0xffffffffu, tmhi, 1));
        tmhi = fmaxf(tmhi, __shfl_xor_sync(0xffffffffu, tmhi, 2));

        const float mnlo = fmaxf(m_lo, tmlo);
        const float mnhi = fmaxf(m_hi, tmhi);
        const float corrlo = __expf(m_lo - mnlo);
        const float corrhi = __expf(m_hi - mnhi);
        m_lo = mnlo; m_hi = mnhi;

        float pslo = 0.f, pshi = 0.f;
#pragma unroll
        for (int nt = 0; nt < 16; nt++) {
            s[nt][0] = __expf(s[nt][0] - mnlo);
            s[nt][1] = __expf(s[nt][1] - mnlo);
            s[nt][2] = __expf(s[nt][2] - mnhi);
            s[nt][3] = __expf(s[nt][3] - mnhi);
            pslo += s[nt][0] + s[nt][1];
            pshi += s[nt][2] + s[nt][3];
        }
        pslo += __shfl_xor_sync(0xffffffffu, pslo, 1);
        pslo += __shfl_xor_sync(0xffffffffu, pslo, 2);
        pshi += __shfl_xor_sync(0xffffffffu, pshi, 1);
        pshi += __shfl_xor_sync(0xffffffffu, pshi, 2);
        l_lo = l_lo * corrlo + pslo;
        l_hi = l_hi * corrhi + pshi;

#pragma unroll
        for (int nt = 0; nt < 8; nt++) {
            o[nt][0] *= corrlo; o[nt][1] *= corrlo;
            o[nt][2] *= corrhi; o[nt][3] *= corrhi;
        }

        // ---- O += P @ V (3-pass split; P from registers) ----
#pragma unroll
        for (int t8 = 0; t8 < 8; t8++) {
            uint32_t ph[4], pl[4];
#pragma unroll
            for (int half = 0; half < 2; half++) {
                const float p0 = s[2 * t8 + half][0];
                const float p1 = s[2 * t8 + half][1];
                const float p2 = s[2 * t8 + half][2];
                const float p3 = s[2 * t8 + half][3];
                const __nv_bfloat16 h0 = __float2bfloat16(p0);
                const __nv_bfloat16 h1 = __float2bfloat16(p1);
                const __nv_bfloat16 h2 = __float2bfloat16(p2);
                const __nv_bfloat16 h3 = __float2bfloat16(p3);
                ph[half * 2 + 0] = pk2(__bfloat162float(h0), __bfloat162float(h1));
                ph[half * 2 + 1] = pk2(__bfloat162float(h2), __bfloat162float(h3));
                pl[half * 2 + 0] = pk2(p0 - __bfloat162float(h0),
                                       p1 - __bfloat162float(h1));
                pl[half * 2 + 1] = pk2(p2 - __bfloat162float(h2),
                                       p3 - __bfloat162float(h3));
            }
            // swap to PTX a-frag order: {rlo klo, rhi klo, rlo khi, rhi khi}
            uint32_t ah[4] = {ph[0], ph[1], ph[2], ph[3]};
            uint32_t al[4] = {pl[0], pl[1], pl[2], pl[3]};

            const uint32_t va = stg + 2 * ATT_MAT +
                ((lane & 7) + 8 * ((lane >> 3) & 1) + t8 * 16) * ATT_LD +
                ((lane >> 4) & 1) * 16;
#pragma unroll
            for (int nt2 = 0; nt2 < 4; nt2++) {
                uint32_t vh[4], vl[4];
                ldsm_x4t(vh, va + nt2 * 32);
                ldsm_x4t(vl, va + ATT_MAT + nt2 * 32);
                mma16816(o[2 * nt2],     ah, vh);
                mma16816(o[2 * nt2],     ah, vl);
                mma16816(o[2 * nt2],     al, vh);
                mma16816(o[2 * nt2 + 1], ah, vh + 2);
                mma16816(o[2 * nt2 + 1], ah, vl + 2);
                mma16816(o[2 * nt2 + 1], al, vh + 2);
            }
        }
        __syncthreads();
    }
#undef LOAD_STAGE_ATT

    // ---- normalize + split-store ----
    const float invlo = 1.f / l_lo;
    const float invhi = 1.f / l_hi;
    const size_t rlo = rowbase + q0 + wid * 16 + (lane >> 2);
    const int colb = h * D_ + (lane & 3) * 2;
#pragma unroll
    for (int nt = 0; nt < 8; nt++) {
        const int col = colb + nt * 8;
        {
            const float v0 = o[nt][0] * invlo, v1 = o[nt][1] * invlo;
            const __nv_bfloat16 h0 = __float2bfloat16(v0);
            const __nv_bfloat16 h1 = __float2bfloat16(v1);
            const size_t off = rlo * C_ + col;
            *reinterpret_cast<uint32_t*>(ohi + off) =
                pk2(__bfloat162float(h0), __bfloat162float(h1));
            *reinterpret_cast<uint32_t*>(olo + off) =
                pk2(v0 - __bfloat162float(h0), v1 - __bfloat162float(h1));
        }
        {
            const float v0 = o[nt][2] * invhi, v1 = o[nt][3] * invhi;
            const __nv_bfloat16 h0 = __float2bfloat16(v0);
            const __nv_bfloat16 h1 = __float2bfloat16(v1);
            const size_t off = (rlo + 8) * C_ + col;
            *reinterpret_cast<uint32_t*>(ohi + off) =
                pk2(__bfloat162float(h0), __bfloat162float(h1));
            *reinterpret_cast<uint32_t*>(olo + off) =
                pk2(v0 - __bfloat162float(h0), v1 - __bfloat162float(h1));
        }
    }
}

// ----------------------------- launch -------------------------------------
extern "C" void kernel_launch(void* const* d_in, const int* in_sizes, int n_in,
                              void* d_out, int out_size) {
    const float* x      = (const float*)d_in[0];
    const float* w_qkv  = (const float*)d_in[1];
    const float* w_proj = (const float*)d_in[2];
    const float* b_proj = (const float*)d_in[3];
    float* out = (float*)d_out;

    __nv_bfloat16 *xhi, *xlo, *whiT, *wloT, *phiT, *ploT;
    __nv_bfloat16 *qhi, *qlo, *ahi, *alo;
    cudaGetSymbolAddress((void**)&xhi,  g_xhi);
    cudaGetSymbolAddress((void**)&xlo,  g_xlo);
    cudaGetSymbolAddress((void**)&whiT, g_whiT);
    cudaGetSymbolAddress((void**)&wloT, g_wloT);
    cudaGetSymbolAddress((void**)&phiT, g_phiT);
    cudaGetSymbolAddress((void**)&ploT, g_ploT);
    cudaGetSymbolAddress((void**)&qhi,  g_qkvhi);
    cudaGetSymbolAddress((void**)&qlo,  g_qkvlo);
    cudaGetSymbolAddress((void**)&ahi,  g_ahi);
    cudaGetSymbolAddress((void**)&alo,  g_alo);

    cudaFuncSetAttribute((const void*)mma_gemm<false, true>,
                         cudaFuncAttributeMaxDynamicSharedMemorySize, GEMM_SMEM);
    cudaFuncSetAttribute((const void*)mma_gemm<true, false>,
                         cudaFuncAttributeMaxDynamicSharedMemorySize, GEMM_SMEM);
    cudaFuncSetAttribute((const void*)attn_mma,
                         cudaFuncAttributeMaxDynamicSharedMemorySize, ATT_SMEM);

    // 0) splits
    {
        int n4 = (M_ * C_) / 4;
        split_ew<<<(n4 + 255) / 256, 256>>>((const float4*)x, xhi, xlo, n4);
        dim3 blk(32, 8);
        dim3 g1(QKVC_ / 32, C_ / 32);
        split_transpose<<<g1, blk>>>(w_qkv, whiT, wloT, C_, QKVC_);
        dim3 g2(C_ / 32, C_ / 32);
        split_transpose<<<g2, blk>>>(w_proj, phiT, ploT, C_, C_);
    }
    // 1) QKV projection -> split bf16, Q pre-scaled by 0.125
    {
        dim3 grid(QKVC_ / 128, M_ / 128);
        mma_gemm<false, true><<<grid, 256, GEMM_SMEM>>>(
            xhi, xlo, whiT, wloT, nullptr, nullptr, qhi, qlo, C_, QKVC_, C_);
    }
    // 2) attention (tensor cores) -> split bf16 output
    {
        dim3 grid(N_ / 128, B_ * H_);
        attn_mma<<<grid, 256, ATT_SMEM>>>(qhi, qlo, ahi, alo);
    }
    // 3) output projection + bias -> fp32 out
    {
        dim3 grid(C_ / 128, M_ / 128);
        mma_gemm<true, false><<<grid, 256, GEMM_SMEM>>>(
            ahi, alo, phiT, ploT, b_proj, out, nullptr, nullptr, 0, C_, C_);
    }
}

// round 6
// speedup vs baseline: 4.7066x; 1.0790x over previous
#include <cuda_runtime.h>
#include <cuda_bf16.h>
#include <math.h>
#include <stdint.h>

#define B_ 8
#define N_ 1024
#define C_ 768
#define H_ 12
#define D_ 64
#define QKVC_ (3 * C_)
#define M_ (B_ * N_)

// ----------------------------- scratch ------------------------------------
__device__ __nv_bfloat16 g_xhi[M_ * C_],     g_xlo[M_ * C_];
__device__ __nv_bfloat16 g_whiT[QKVC_ * C_], g_wloT[QKVC_ * C_];
__device__ __nv_bfloat16 g_phiT[C_ * C_],    g_ploT[C_ * C_];
__device__ __nv_bfloat16 g_qkvhi[M_ * QKVC_], g_qkvlo[M_ * QKVC_];
__device__ __nv_bfloat16 g_ahi[M_ * C_],     g_alo[M_ * C_];

// ----------------------------- helpers ------------------------------------
__device__ __forceinline__ uint32_t smem_u32(const void* p) {
    uint32_t a;
    asm("{ .reg .u64 t; cvta.to.shared.u64 t, %1; cvt.u32.u64 %0, t; }"
        : "=r"(a) : "l"(p));
    return a;
}
__device__ __forceinline__ void cp16(uint32_t s, const void* g) {
    asm volatile("cp.async.cg.shared.global [%0], [%1], 16;"
                 :: "r"(s), "l"(g) : "memory");
}
#define CP_COMMIT() asm volatile("cp.async.commit_group;" ::: "memory")
#define CP_WAIT(n)  asm volatile("cp.async.wait_group %0;" :: "n"(n) : "memory")

__device__ __forceinline__ void ldsm_x4(uint32_t* f, uint32_t a) {
    asm volatile("ldmatrix.sync.aligned.m8n8.x4.shared.b16 {%0,%1,%2,%3}, [%4];"
                 : "=r"(f[0]), "=r"(f[1]), "=r"(f[2]), "=r"(f[3]) : "r"(a));
}
__device__ __forceinline__ void ldsm_x4t(uint32_t* f, uint32_t a) {
    asm volatile("ldmatrix.sync.aligned.m8n8.x4.trans.shared.b16 {%0,%1,%2,%3}, [%4];"
                 : "=r"(f[0]), "=r"(f[1]), "=r"(f[2]), "=r"(f[3]) : "r"(a));
}
__device__ __forceinline__ void ldsm_x2(uint32_t* f, uint32_t a) {
    asm volatile("ldmatrix.sync.aligned.m8n8.x2.shared.b16 {%0,%1}, [%2];"
                 : "=r"(f[0]), "=r"(f[1]) : "r"(a));
}
__device__ __forceinline__ void mma16816(float* d, const uint32_t* a,
                                         const uint32_t* b) {
    asm volatile(
        "mma.sync.aligned.m16n8k16.row.col.f32.bf16.bf16.f32 "
        "{%0,%1,%2,%3}, {%4,%5,%6,%7}, {%8,%9}, {%0,%1,%2,%3};"
        : "+f"(d[0]), "+f"(d[1]), "+f"(d[2]), "+f"(d[3])
        : "r"(a[0]), "r"(a[1]), "r"(a[2]), "r"(a[3]), "r"(b[0]), "r"(b[1]));
}
__device__ __forceinline__ uint32_t pk2(float f0, float f1) {
    __nv_bfloat162 h = __floats2bfloat162_rn(f0, f1);
    return *reinterpret_cast<uint32_t*>(&h);
}

// ----------------------------- split kernels ------------------------------
__global__ void split_ew(const float4* __restrict__ s,
                         __nv_bfloat16* __restrict__ hi,
                         __nv_bfloat16* __restrict__ lo, int n4) {
    int i = blockIdx.x * blockDim.x + threadIdx.x;
    if (i >= n4) return;
    float4 v = s[i];
    float a[4] = {v.x, v.y, v.z, v.w};
    __align__(8) __nv_bfloat16 h[4];
    __align__(8) __nv_bfloat16 l[4];
#pragma unroll
    for (int j = 0; j < 4; j++) {
        h[j] = __float2bfloat16(a[j]);
        l[j] = __float2bfloat16(a[j] - __bfloat162float(h[j]));
    }
    *reinterpret_cast<uint2*>(hi + (size_t)i * 4) = *reinterpret_cast<uint2*>(h);
    *reinterpret_cast<uint2*>(lo + (size_t)i * 4) = *reinterpret_cast<uint2*>(l);
}

__global__ void split_transpose(const float* __restrict__ w,
                                __nv_bfloat16* __restrict__ hiT,
                                __nv_bfloat16* __restrict__ loT, int K, int N) {
    __shared__ float t[32][33];
    const int n0 = blockIdx.x * 32, k0 = blockIdx.y * 32;
    for (int r = threadIdx.y; r < 32; r += 8)
        t[r][threadIdx.x] = w[(size_t)(k0 + r) * N + n0 + threadIdx.x];
    __syncthreads();
    for (int r = threadIdx.y; r < 32; r += 8) {
        float v = t[threadIdx.x][r];
        __nv_bfloat16 h = __float2bfloat16(v);
        __nv_bfloat16 l = __float2bfloat16(v - __bfloat162float(h));
        size_t o = (size_t)(n0 + r) * K + k0 + threadIdx.x;
        hiT[o] = h; loT[o] = l;
    }
}

// ----------------------------- mma.sync GEMM -------------------------------
// BK=64, 2-stage cp.async, fragment double-buffer, pass-major MMA order.
#define BK_ 64
#define LROW_ 144                        // 128B data + 16B pad (9x16B, odd)
#define MATB_ (128 * LROW_)              // 18432
#define STGB_ (4 * MATB_)                // 73728
#define GEMM_SMEM (2 * STGB_)            // 147456

template <bool BIAS, bool SPLITOUT>
__global__ __launch_bounds__(256, 1)
void mma_gemm(const __nv_bfloat16* __restrict__ Ahi,
              const __nv_bfloat16* __restrict__ Alo,
              const __nv_bfloat16* __restrict__ BhiT,
              const __nv_bfloat16* __restrict__ BloT,
              const float* __restrict__ bias,
              float* __restrict__ Cf,
              __nv_bfloat16* __restrict__ Chi,
              __nv_bfloat16* __restrict__ Clo,
              int scale_cols, int Nn, int K) {
    extern __shared__ char smem[];
    const uint32_t sb = smem_u32(smem);
    const int tid = threadIdx.x;
    const int wid = tid >> 5;
    const int lane = tid & 31;
    const int row0 = blockIdx.y * 128;
    const int col0 = blockIdx.x * 128;
    const int wm = (wid >> 2) * 64;
    const int wn = (wid & 3) * 32;

    float acc[4][4][4];
#pragma unroll
    for (int i = 0; i < 4; i++)
#pragma unroll
        for (int j = 0; j < 4; j++)
#pragma unroll
            for (int k = 0; k < 4; k++) acc[i][j][k] = 0.f;

#define LOAD_STAGE(cc, ss)                                                   \
    {                                                                        \
        const uint32_t base = sb + (ss) * STGB_;                             \
        const int k0 = (cc) * BK_;                                           \
        _Pragma("unroll")                                                    \
        for (int t = 0; t < 16; t++) {                                       \
            const int idx = tid + t * 256;                                   \
            const int mat = idx >> 10, rem = idx & 1023;                     \
            const int r = rem >> 3, c8 = rem & 7;                            \
            const uint32_t off = (uint32_t)(mat * MATB_ + r * LROW_ + c8 * 16); \
            const __nv_bfloat16* src;                                        \
            if (mat == 0)      src = Ahi  + (size_t)(row0 + r) * K + k0 + c8 * 8; \
            else if (mat == 1) src = Alo  + (size_t)(row0 + r) * K + k0 + c8 * 8; \
            else if (mat == 2) src = BhiT + (size_t)(col0 + r) * K + k0 + c8 * 8; \
            else               src = BloT + (size_t)(col0 + r) * K + k0 + c8 * 8; \
            cp16(base + off, src);                                           \
        }                                                                    \
        CP_COMMIT();                                                         \
    }

#define LDFRAG(buf, kk)                                                     \
    {                                                                       \
        const uint32_t acol = (uint32_t)(((kk) * 16 + (lane >> 4) * 8) * 2);\
        const uint32_t bcol =                                               \
            (uint32_t)(((kk) * 16 + ((lane >> 3) & 1) * 8) * 2);            \
        _Pragma("unroll")                                                   \
        for (int mt = 0; mt < 4; mt++) {                                    \
            const uint32_t arow =                                           \
                (uint32_t)((wm + mt * 16 + (lane & 15)) * LROW_);           \
            ldsm_x4(ah[buf][mt], stg + arow + acol);                        \
            ldsm_x4(al[buf][mt], stg + MATB_ + arow + acol);                \
        }                                                                   \
        _Pragma("unroll")                                                   \
        for (int nt = 0; nt < 4; nt++) {                                    \
            const uint32_t brow =                                           \
                (uint32_t)((wn + nt * 8 + (lane & 7)) * LROW_);             \
            ldsm_x2(bh[buf][nt], stg + 2 * MATB_ + brow + bcol);            \
            ldsm_x2(bl[buf][nt], stg + 3 * MATB_ + brow + bcol);            \
        }                                                                   \
    }

    const int nch = K / BK_;    // 12
    LOAD_STAGE(0, 0);

    for (int c = 0; c < nch; c++) {
        const int cur = c & 1;
        if (c + 1 < nch) {
            LOAD_STAGE(c + 1, 1 - cur);
            CP_WAIT(1);
        } else {
            CP_WAIT(0);
        }
        __syncthreads();

        const uint32_t stg = sb + cur * STGB_;
        uint32_t ah[2][4][4], al[2][4][4], bh[2][4][2], bl[2][4][2];
        LDFRAG(0, 0);
#pragma unroll
        for (int kk = 0; kk < 4; kk++) {
            const int cb = kk & 1;
            if (kk < 3) {
                const int nb = 1 - cb;
                LDFRAG(nb, kk + 1);
            }
            // pass-major MMA: dependent chains 16 apart
#pragma unroll
            for (int mt = 0; mt < 4; mt++)
#pragma unroll
                for (int nt = 0; nt < 4; nt++)
                    mma16816(acc[mt][nt], ah[cb][mt], bh[cb][nt]);
#pragma unroll
            for (int mt = 0; mt < 4; mt++)
#pragma unroll
                for (int nt = 0; nt < 4; nt++)
                    mma16816(acc[mt][nt], ah[cb][mt], bl[cb][nt]);
#pragma unroll
            for (int mt = 0; mt < 4; mt++)
#pragma unroll
                for (int nt = 0; nt < 4; nt++)
                    mma16816(acc[mt][nt], al[cb][mt], bh[cb][nt]);
        }
        __syncthreads();
    }
#undef LOAD_STAGE
#undef LDFRAG

    const int g = lane >> 2, t4 = lane & 3;
#pragma unroll
    for (int nt = 0; nt < 4; nt++) {
        const int col = col0 + wn + nt * 8 + t4 * 2;
        if (SPLITOUT) {
            const float sc = (col < scale_cols) ? 0.125f : 1.0f;
#pragma unroll
            for (int mt = 0; mt < 4; mt++) {
                const int ra = row0 + wm + mt * 16 + g;
#pragma unroll
                for (int half = 0; half < 2; half++) {
                    const int r = ra + half * 8;
                    const float v0 = acc[mt][nt][half * 2 + 0] * sc;
                    const float v1 = acc[mt][nt][half * 2 + 1] * sc;
                    __nv_bfloat16 h0 = __float2bfloat16(v0);
                    __nv_bfloat16 h1 = __float2bfloat16(v1);
                    const float l0 = v0 - __bfloat162float(h0);
                    const float l1 = v1 - __bfloat162float(h1);
                    const size_t off = (size_t)r * Nn + col;
                    *reinterpret_cast<uint32_t*>(Chi + off) =
                        pk2(__bfloat162float(h0), __bfloat162float(h1));
                    *reinterpret_cast<uint32_t*>(Clo + off) = pk2(l0, l1);
                }
            }
        } else {
            float b0 = 0.f, b1 = 0.f;
            if (BIAS) { b0 = bias[col]; b1 = bias[col + 1]; }
#pragma unroll
            for (int mt = 0; mt < 4; mt++) {
                const int ra = row0 + wm + mt * 16 + g;
                float2 v0 = make_float2(acc[mt][nt][0] + b0, acc[mt][nt][1] + b1);
                float2 v1 = make_float2(acc[mt][nt][2] + b0, acc[mt][nt][3] + b1);
                *reinterpret_cast<float2*>(&Cf[(size_t)ra * Nn + col]) = v0;
                *reinterpret_cast<float2*>(&Cf[(size_t)(ra + 8) * Nn + col]) = v1;
            }
        }
    }
}

// ----------------------------- mma flash attention -------------------------
#define ATT_LD 144
#define ATT_MAT 18432
#define ATT_STG0 (2 * ATT_MAT)
#define ATT_STGSZ (4 * ATT_MAT)
#define ATT_SMEM (ATT_STG0 + 2 * ATT_STGSZ)  // 184320

__global__ __launch_bounds__(256, 1)
void attn_mma(const __nv_bfloat16* __restrict__ qhi,
              const __nv_bfloat16* __restrict__ qlo,
              __nv_bfloat16* __restrict__ ohi,
              __nv_bfloat16* __restrict__ olo) {
    extern __shared__ char smem[];
    const uint32_t sb = smem_u32(smem);
    const int tid = threadIdx.x, wid = tid >> 5, lane = tid & 31;
    const int b = blockIdx.y / H_, h = blockIdx.y % H_;
    const int q0 = blockIdx.x * 128;
    const size_t rowbase = (size_t)b * N_;

    // ---- load Q (hi/lo) ----
#pragma unroll
    for (int t = 0; t < 8; t++) {
        const int idx = tid + t * 256;
        const int mat = idx >> 10, rem = idx & 1023;
        const int r = rem >> 3, c = rem & 7;
        const uint32_t so = sb + mat * ATT_MAT + r * ATT_LD + c * 16;
        const __nv_bfloat16* src =
            (mat ? qlo : qhi) + ((rowbase + q0 + r) * QKVC_ + h * D_ + c * 8);
        cp16(so, src);
    }

#define LOAD_STAGE_ATT(ktile, ss)                                            \
    {                                                                        \
        const uint32_t base = sb + ATT_STG0 + (ss) * ATT_STGSZ;              \
        const size_t krow = rowbase + (ktile) * 128;                         \
        _Pragma("unroll")                                                    \
        for (int t = 0; t < 16; t++) {                                       \
            const int idx = tid + t * 256;                                   \
            const int mat = idx >> 10, rem = idx & 1023;                     \
            const int r = rem >> 3, c = rem & 7;                             \
            const uint32_t so = base + mat * ATT_MAT + r * ATT_LD + c * 16;  \
            const __nv_bfloat16* sp = ((mat & 1) ? qlo : qhi) +              \
                ((krow + r) * QKVC_ + ((mat >> 1) ? 2 * C_ : C_) +           \
                 h * D_ + c * 8);                                            \
            cp16(so, sp);                                                    \
        }                                                                    \
        CP_COMMIT();                                                         \
    }

    LOAD_STAGE_ATT(0, 0);

    float m_lo = -INFINITY, m_hi = -INFINITY, l_lo = 0.f, l_hi = 0.f;
    float o[8][4];
#pragma unroll
    for (int i = 0; i < 8; i++)
#pragma unroll
        for (int j = 0; j < 4; j++) o[i][j] = 0.f;

    const uint32_t qa =
        sb + (wid * 16 + (lane & 15)) * ATT_LD + ((lane >> 4) * 8) * 2;

    for (int kt = 0; kt < N_ / 128; kt++) {
        if (kt + 1 < N_ / 128) {
            LOAD_STAGE_ATT(kt + 1, (kt + 1) & 1);
            CP_WAIT(1);
        } else {
            CP_WAIT(0);
        }
        __syncthreads();

        const uint32_t stg = sb + ATT_STG0 + (kt & 1) * ATT_STGSZ;

        // ---- S = Q @ K^T (3-pass split), blocked frags, pass-major ----
        float s[16][4];
#pragma unroll
        for (int nt = 0; nt < 16; nt++)
#pragma unroll
            for (int j = 0; j < 4; j++) s[nt][j] = 0.f;

#pragma unroll
        for (int k4 = 0; k4 < 4; k4++) {
            uint32_t qh[4], ql[4];
            ldsm_x4(qh, qa + k4 * 32);
            ldsm_x4(ql, qa + ATT_MAT + k4 * 32);
            const uint32_t ka = stg + (lane & 7) * ATT_LD +
                                (k4 * 16 + ((lane >> 3) & 1) * 8) * 2;
#pragma unroll
            for (int blk = 0; blk < 2; blk++) {
                uint32_t kh[8][2], kl[8][2];
#pragma unroll
                for (int j = 0; j < 8; j++) {
                    const int nt = blk * 8 + j;
                    ldsm_x2(kh[j], ka + nt * 8 * ATT_LD);
                    ldsm_x2(kl[j], ka + ATT_MAT + nt * 8 * ATT_LD);
                }
#pragma unroll
                for (int j = 0; j < 8; j++)
                    mma16816(s[blk * 8 + j], qh, kh[j]);
#pragma unroll
                for (int j = 0; j < 8; j++)
                    mma16816(s[blk * 8 + j], qh, kl[j]);
#pragma unroll
                for (int j = 0; j < 8; j++)
                    mma16816(s[blk * 8 + j], ql, kh[j]);
            }
        }

        // ---- online softmax ----
        float tmlo = -INFINITY, tmhi = -INFINITY;
#pragma unroll
        for (int nt = 0; nt < 16; nt++) {
            tmlo = fmaxf(tmlo, fmaxf(s[nt][0], s[nt][1]));
            tmhi = fmaxf(tmhi, fmaxf(s[nt][2], s[nt][3]));
        }
        tmlo = fmaxf(tmlo, __shfl_xor_sync(0xffffffffu, tmlo, 1));
        tmlo = fmaxf(tmlo, __shfl_xor_sync(0xffffffffu, tmlo, 2));
        tmhi = fmaxf(tmhi, __shfl_xor_sync(0xffffffffu, tmhi, 1));
        tmhi = fmaxf(tmhi, __shfl_xor_sync(0xffffffffu, tmhi, 2));

        const float mnlo = fmaxf(m_lo, tmlo);
        const float mnhi = fmaxf(m_hi, tmhi);
        const float corrlo = __expf(m_lo - mnlo);
        const float corrhi = __expf(m_hi - mnhi);
        m_lo = mnlo; m_hi = mnhi;

        float pslo = 0.f, pshi = 0.f;
#pragma unroll
        for (int nt = 0; nt < 16; nt++) {
            s[nt][0] = __expf(s[nt][0] - mnlo);
            s[nt][1] = __expf(s[nt][1] - mnlo);
            s[nt][2] = __expf(s[nt][2] - mnhi);
            s[nt][3] = __expf(s[nt][3] - mnhi);
            pslo += s[nt][0] + s[nt][1];
            pshi += s[nt][2] + s[nt][3];
        }
        pslo += __shfl_xor_sync(0xffffffffu, pslo, 1);
        pslo += __shfl_xor_sync(0xffffffffu, pslo, 2);
        pshi += __shfl_xor_sync(0xffffffffu, pshi, 1);
        pshi += __shfl_xor_sync(0xffffffffu, pshi, 2);
        l_lo = l_lo * corrlo + pslo;
        l_hi = l_hi * corrhi + pshi;

#pragma unroll
        for (int nt = 0; nt < 8; nt++) {
            o[nt][0] *= corrlo; o[nt][1] *= corrlo;
            o[nt][2] *= corrhi; o[nt][3] *= corrhi;
        }

        // ---- O += P @ V (blocked V frags, pass-major) ----
#pragma unroll
        for (int t8 = 0; t8 < 8; t8++) {
            uint32_t ah[4], al[4];
#pragma unroll
            for (int half = 0; half < 2; half++) {
                const float p0 = s[2 * t8 + half][0];
                const float p1 = s[2 * t8 + half][1];
                const float p2 = s[2 * t8 + half][2];
                const float p3 = s[2 * t8 + half][3];
                const __nv_bfloat16 h0 = __float2bfloat16(p0);
                const __nv_bfloat16 h1 = __float2bfloat16(p1);
                const __nv_bfloat16 h2 = __float2bfloat16(p2);
                const __nv_bfloat16 h3 = __float2bfloat16(p3);
                ah[half * 2 + 0] = pk2(__bfloat162float(h0), __bfloat162float(h1));
                ah[half * 2 + 1] = pk2(__bfloat162float(h2), __bfloat162float(h3));
                al[half * 2 + 0] = pk2(p0 - __bfloat162float(h0),
                                       p1 - __bfloat162float(h1));
                al[half * 2 + 1] = pk2(p2 - __bfloat162float(h2),
                                       p3 - __bfloat162float(h3));
            }

            const uint32_t va = stg + 2 * ATT_MAT +
                ((lane & 7) + 8 * ((lane >> 3) & 1) + t8 * 16) * ATT_LD +
                ((lane >> 4) & 1) * 16;
            uint32_t vh[4][4], vl[4][4];
#pragma unroll
            for (int nt2 = 0; nt2 < 4; nt2++) {
                ldsm_x4t(vh[nt2], va + nt2 * 32);
                ldsm_x4t(vl[nt2], va + ATT_MAT + nt2 * 32);
            }
#pragma unroll
            for (int nt2 = 0; nt2 < 4; nt2++) {
                mma16816(o[2 * nt2],     ah, vh[nt2]);
                mma16816(o[2 * nt2 + 1], ah, vh[nt2] + 2);
            }
#pragma unroll
            for (int nt2 = 0; nt2 < 4; nt2++) {
                mma16816(o[2 * nt2],     ah, vl[nt2]);
                mma16816(o[2 * nt2 + 1], ah, vl[nt2] + 2);
            }
#pragma unroll
            for (int nt2 = 0; nt2 < 4; nt2++) {
                mma16816(o[2 * nt2],     al, vh[nt2]);
                mma16816(o[2 * nt2 + 1], al, vh[nt2] + 2);
            }
        }
        __syncthreads();
    }
#undef LOAD_STAGE_ATT

    // ---- normalize + split-store ----
    const float invlo = 1.f / l_lo;
    const float invhi = 1.f / l_hi;
    const size_t rlo = rowbase + q0 + wid * 16 + (lane >> 2);
    const int colb = h * D_ + (lane & 3) * 2;
#pragma unroll
    for (int nt = 0; nt < 8; nt++) {
        const int col = colb + nt * 8;
        {
            const float v0 = o[nt][0] * invlo, v1 = o[nt][1] * invlo;
            const __nv_bfloat16 h0 = __float2bfloat16(v0);
            const __nv_bfloat16 h1 = __float2bfloat16(v1);
            const size_t off = rlo * C_ + col;
            *reinterpret_cast<uint32_t*>(ohi + off) =
                pk2(__bfloat162float(h0), __bfloat162float(h1));
            *reinterpret_cast<uint32_t*>(olo + off) =
                pk2(v0 - __bfloat162float(h0), v1 - __bfloat162float(h1));
        }
        {
            const float v0 = o[nt][2] * invhi, v1 = o[nt][3] * invhi;
            const __nv_bfloat16 h0 = __float2bfloat16(v0);
            const __nv_bfloat16 h1 = __float2bfloat16(v1);
            const size_t off = (rlo + 8) * C_ + col;
            *reinterpret_cast<uint32_t*>(ohi + off) =
                pk2(__bfloat162float(h0), __bfloat162float(h1));
            *reinterpret_cast<uint32_t*>(olo + off) =
                pk2(v0 - __bfloat162float(h0), v1 - __bfloat162float(h1));
        }
    }
}

// ----------------------------- launch -------------------------------------
extern "C" void kernel_launch(void* const* d_in, const int* in_sizes, int n_in,
                              void* d_out, int out_size) {
    const float* x      = (const float*)d_in[0];
    const float* w_qkv  = (const float*)d_in[1];
    const float* w_proj = (const float*)d_in[2];
    const float* b_proj = (const float*)d_in[3];
    float* out = (float*)d_out;

    __nv_bfloat16 *xhi, *xlo, *whiT, *wloT, *phiT, *ploT;
    __nv_bfloat16 *qhi, *qlo, *ahi, *alo;
    cudaGetSymbolAddress((void**)&xhi,  g_xhi);
    cudaGetSymbolAddress((void**)&xlo,  g_xlo);
    cudaGetSymbolAddress((void**)&whiT, g_whiT);
    cudaGetSymbolAddress((void**)&wloT, g_wloT);
    cudaGetSymbolAddress((void**)&phiT, g_phiT);
    cudaGetSymbolAddress((void**)&ploT, g_ploT);
    cudaGetSymbolAddress((void**)&qhi,  g_qkvhi);
    cudaGetSymbolAddress((void**)&qlo,  g_qkvlo);
    cudaGetSymbolAddress((void**)&ahi,  g_ahi);
    cudaGetSymbolAddress((void**)&alo,  g_alo);

    cudaFuncSetAttribute((const void*)mma_gemm<false, true>,
                         cudaFuncAttributeMaxDynamicSharedMemorySize, GEMM_SMEM);
    cudaFuncSetAttribute((const void*)mma_gemm<true, false>,
                         cudaFuncAttributeMaxDynamicSharedMemorySize, GEMM_SMEM);
    cudaFuncSetAttribute((const void*)attn_mma,
                         cudaFuncAttributeMaxDynamicSharedMemorySize, ATT_SMEM);

    // 0) splits
    {
        int n4 = (M_ * C_) / 4;
        split_ew<<<(n4 + 255) / 256, 256>>>((const float4*)x, xhi, xlo, n4);
        dim3 blk(32, 8);
        dim3 g1(QKVC_ / 32, C_ / 32);
        split_transpose<<<g1, blk>>>(w_qkv, whiT, wloT, C_, QKVC_);
        dim3 g2(C_ / 32, C_ / 32);
        split_transpose<<<g2, blk>>>(w_proj, phiT, ploT, C_, C_);
    }
    // 1) QKV projection -> split bf16, Q pre-scaled by 0.125
    {
        dim3 grid(QKVC_ / 128, M_ / 128);
        mma_gemm<false, true><<<grid, 256, GEMM_SMEM>>>(
            xhi, xlo, whiT, wloT, nullptr, nullptr, qhi, qlo, C_, QKVC_, C_);
    }
    // 2) attention (tensor cores) -> split bf16 output
    {
        dim3 grid(N_ / 128, B_ * H_);
        attn_mma<<<grid, 256, ATT_SMEM>>>(qhi, qlo, ahi, alo);
    }
    // 3) output projection + bias -> fp32 out
    {
        dim3 grid(C_ / 128, M_ / 128);
        mma_gemm<true, false><<<grid, 256, GEMM_SMEM>>>(
            ahi, alo, phiT, ploT, b_proj, out, nullptr, nullptr, 0, C_, C_);
    }
}